// round 4
// baseline (speedup 1.0000x reference)
#include <cuda_runtime.h>

#define N_NODES 100000
#define E_EDGES 3200000
#define HIDF    128
#define GG      64
#define BN_EPS  1e-5f
#define NB_SCAN 391   // ceil(N_NODES/256)

// ---------------- static device scratch (no runtime allocations) -------------
__device__ int   g_is64;                          // 1 if index inputs are int64
__device__ float g_dis[N_NODES];                  // rsqrt(degree)
__device__ int   g_hist[N_NODES];                 // in-degree (excl self-loop)
__device__ int   g_off[N_NODES];                  // exclusive prefix of hist
__device__ int   g_cursor[N_NODES];               // placement cursors
__device__ int   g_bsum[512];                     // block sums for scan
__device__ int   g_row[E_EDGES];
__device__ int   g_col[E_EDGES];
__device__ int   g_srow[E_EDGES];                 // source rows sorted by dest
__device__ __align__(16) float g_xw[(size_t)N_NODES * HIDF];   // transformed feats
__device__ __align__(16) float g_hbuf[3u * N_NODES * HIDF];    // per-layer pre-ReLU
__device__ __align__(16) float g_Wp[3 * 2 * 64 * 64];          // BN-folded weights
__device__ __align__(16) float g_bp[3 * HIDF];                 // BN-folded bias
__device__ float g_pooled[GG * 3 * HIDF];
__device__ int   g_cnt[GG];
__device__ int   g_start[GG];

// ---------------- dtype detection -------------------------------------------
// If inputs are int64 (values < 2^31), every odd 32-bit word of the first 64
// entries is zero. Random int32 edge data makes that essentially impossible.
__global__ void k_detect(const int* __restrict__ ei32) {
    if (threadIdx.x == 0 && blockIdx.x == 0) {
        int odd_zero = 1;
        for (int i = 0; i < 64; i++)
            if (ei32[2 * i + 1] != 0) odd_zero = 0;
        g_is64 = odd_zero;
    }
}

// ---------------- init -------------------------------------------------------
__global__ void k_init() {
    int i = blockIdx.x * blockDim.x + threadIdx.x;
    if (i < N_NODES) g_hist[i] = 0;
    if (i < GG) { g_cnt[i] = 0; g_start[i] = 0; }
}

// edge load: -> int32 row/col, histogram over destination
__global__ void k_edge(const void* __restrict__ eiv) {
    int e = blockIdx.x * blockDim.x + threadIdx.x;
    if (e >= E_EDGES) return;
    int r, c;
    if (g_is64) {
        const long long* ei = (const long long*)eiv;
        r = (int)ei[e];
        c = (int)ei[(size_t)E_EDGES + e];
    } else {
        const int* ei = (const int*)eiv;
        r = ei[e];
        c = ei[E_EDGES + e];
    }
    g_row[e] = r;
    g_col[e] = c;
    atomicAdd(&g_hist[c], 1);
}

// dis = rsqrt(deg), deg = in-edges + 1 self-loop (always >= 1)
__global__ void k_rsqrt() {
    int i = blockIdx.x * blockDim.x + threadIdx.x;
    if (i < N_NODES) g_dis[i] = rsqrtf((float)(g_hist[i] + 1));
}

// ---------------- two-level exclusive scan of g_hist -> g_off ----------------
__global__ void __launch_bounds__(256) k_scan1() {
    __shared__ int sh[256];
    int b = blockIdx.x, t = threadIdx.x;
    int i = b * 256 + t;
    int v = (i < N_NODES) ? g_hist[i] : 0;
    sh[t] = v;
    __syncthreads();
    for (int o = 1; o < 256; o <<= 1) {
        int u = (t >= o) ? sh[t - o] : 0;
        __syncthreads();
        sh[t] += u;
        __syncthreads();
    }
    if (i < N_NODES) g_off[i] = sh[t] - v;       // exclusive within block
    if (t == 255) g_bsum[b] = sh[255];
}

__global__ void __launch_bounds__(512) k_scan2() {
    __shared__ int sh[512];
    int t = threadIdx.x;
    int v = (t < NB_SCAN) ? g_bsum[t] : 0;
    sh[t] = v;
    __syncthreads();
    for (int o = 1; o < 512; o <<= 1) {
        int u = (t >= o) ? sh[t - o] : 0;
        __syncthreads();
        sh[t] += u;
        __syncthreads();
    }
    if (t < NB_SCAN) g_bsum[t] = sh[t] - v;      // exclusive block offsets
}

__global__ void k_scan3() {
    int i = blockIdx.x * blockDim.x + threadIdx.x;
    if (i >= N_NODES) return;
    int o = g_off[i] + g_bsum[i >> 8];
    g_off[i] = o;
    g_cursor[i] = o;
}

// place source rows into dest-sorted order
__global__ void k_place() {
    int e = blockIdx.x * blockDim.x + threadIdx.x;
    if (e >= E_EDGES) return;
    int c = g_col[e];
    int pos = atomicAdd(&g_cursor[c], 1);
    g_srow[pos] = g_row[e];
}

// ---------------- BN folding -------------------------------------------------
__global__ void k_fold_w(const float* __restrict__ W, const float* __restrict__ gamma,
                         const float* __restrict__ var) {
    int idx = blockIdx.x * blockDim.x + threadIdx.x;
    if (idx >= 3 * 8192) return;
    int l = idx / 8192;
    int rem = idx - l * 8192;
    int p = rem / 4096;
    int j = rem & 63;
    int c = p * 64 + j;
    float sg = gamma[l * HIDF + c] * rsqrtf(var[l * HIDF + c] + BN_EPS);
    g_Wp[idx] = W[idx] * sg;
}

__global__ void k_fold_b(const float* __restrict__ b, const float* __restrict__ gamma,
                         const float* __restrict__ beta, const float* __restrict__ mean,
                         const float* __restrict__ var) {
    int idx = blockIdx.x * blockDim.x + threadIdx.x;
    if (idx >= 3 * HIDF) return;
    float sg = gamma[idx] * rsqrtf(var[idx] + BN_EPS);
    g_bp[idx] = b[idx] * sg + (beta[idx] - mean[idx] * sg);
}

// ---------------- block-diagonal GEMM: xw = relu?(in) @ blkdiag(W0,W1) -------
// 32-row tile, 256 threads. Static shared = 32KB (W) + 16KB (in) = 48KB.
__global__ void __launch_bounds__(256) k_gemm(const float* __restrict__ x,
                                              int src_layer, int layer, int relu_in) {
    __shared__ float sW[8192];        // [2][64][64]
    __shared__ float sIn[32 * HIDF];  // 32 rows x 128
    const float* in = (src_layer < 0) ? x : (g_hbuf + (size_t)src_layer * N_NODES * HIDF);
    int t = threadIdx.x;
    const float4* Wl4 = (const float4*)(g_Wp + layer * 8192);
#pragma unroll
    for (int i = 0; i < 8; i++) {
        int idx = t + i * 256;                 // 2048 float4 of W
        ((float4*)sW)[idx] = Wl4[idx];
    }
    int R0 = blockIdx.x * 32;
#pragma unroll
    for (int i = 0; i < 4; i++) {
        int idx = t + i * 256;                 // 1024 float4 of input tile
        int r = idx >> 5;
        int c4 = idx & 31;
        float4 v = make_float4(0.f, 0.f, 0.f, 0.f);
        if (R0 + r < N_NODES) v = ((const float4*)in)[(size_t)(R0 + r) * 32 + c4];
        if (relu_in) {
            v.x = fmaxf(v.x, 0.f); v.y = fmaxf(v.y, 0.f);
            v.z = fmaxf(v.z, 0.f); v.w = fmaxf(v.w, 0.f);
        }
        ((float4*)sIn)[idx] = v;
    }
    __syncthreads();

    int cg = t & 31;          // 32 column groups x 4 cols = 128 cols
    int rg = t >> 5;          // 8 row groups x 4 rows = 32 rows
    int p = cg >> 4;          // part 0/1
    int c0 = cg * 4;          // output col base
    int jn = c0 & 63;         // col within part
    int r0 = rg * 4;
    float acc[4][4];
#pragma unroll
    for (int i = 0; i < 4; i++) { acc[i][0] = acc[i][1] = acc[i][2] = acc[i][3] = 0.f; }
    const float* sWp = sW + p * 4096;
    const float* sInp = sIn + p * 64;
#pragma unroll 4
    for (int k = 0; k < 64; k++) {
        float4 w = *(const float4*)(sWp + k * 64 + jn);
#pragma unroll
        for (int i = 0; i < 4; i++) {
            float a = sInp[(r0 + i) * HIDF + k];
            acc[i][0] += a * w.x; acc[i][1] += a * w.y;
            acc[i][2] += a * w.z; acc[i][3] += a * w.w;
        }
    }
#pragma unroll
    for (int i = 0; i < 4; i++) {
        int r = R0 + r0 + i;
        if (r < N_NODES)
            *(float4*)(g_xw + (size_t)r * HIDF + c0) =
                make_float4(acc[i][0], acc[i][1], acc[i][2], acc[i][3]);
    }
}

// ---------------- segmented gather-reduce: one warp per destination ----------
__global__ void __launch_bounds__(256) k_aggr(int layer) {
    int node = (blockIdx.x * 256 + threadIdx.x) >> 5;
    if (node >= N_NODES) return;
    int lane = threadIdx.x & 31;
    int s0 = g_off[node];
    int s1 = (node + 1 < N_NODES) ? g_off[node + 1] : E_EDGES;
    float dc = g_dis[node];

    // seed: bias + self-loop (norm = dc*dc)
    float4 b = ((const float4*)g_bp)[layer * 32 + lane];
    float4 xv = ((const float4*)g_xw)[(size_t)node * 32 + lane];
    float dd = dc * dc;
    float4 acc;
    acc.x = b.x + xv.x * dd; acc.y = b.y + xv.y * dd;
    acc.z = b.z + xv.z * dd; acc.w = b.w + xv.w * dd;

    for (int s = s0; s < s1; s += 32) {
        int idx = 0;
        float dr = 0.f;
        if (s + lane < s1) {
            idx = g_srow[s + lane];
            dr = g_dis[idx];
        }
        int cnt = min(32, s1 - s);
        for (int j = 0; j < cnt; j++) {
            int r = __shfl_sync(0xffffffffu, idx, j);
            float nv = dc * __shfl_sync(0xffffffffu, dr, j);
            float4 v = __ldg((const float4*)(g_xw + (size_t)r * HIDF) + lane);
            acc.x += v.x * nv; acc.y += v.y * nv;
            acc.z += v.z * nv; acc.w += v.w * nv;
        }
    }
    ((float4*)(g_hbuf + (size_t)layer * N_NODES * HIDF))[(size_t)node * 32 + lane] = acc;
}

// ---------------- batch counts + segment starts (batch is sorted) ------------
__global__ void k_batch(const void* __restrict__ bv) {
    int i = blockIdx.x * blockDim.x + threadIdx.x;
    if (i >= N_NODES) return;
    int b, bp = -1;
    if (g_is64) {
        const long long* bb = (const long long*)bv;
        b = (int)bb[i];
        if (i > 0) bp = (int)bb[i - 1];
    } else {
        const int* bb = (const int*)bv;
        b = bb[i];
        if (i > 0) bp = bb[i - 1];
    }
    atomicAdd(&g_cnt[b], 1);
    if (i == 0 || bp != b) g_start[b] = i;
}

// ---------------- mean pool with lazy ReLU -----------------------------------
__global__ void __launch_bounds__(128) k_pool() {
    int g = blockIdx.x;
    int l = blockIdx.y;
    int t = threadIdx.x;
    int s = g_start[g];
    int n = g_cnt[g];
    const float* base = g_hbuf + ((size_t)l * N_NODES + s) * HIDF + t;
    float acc = 0.f;
    for (int j = 0; j < n; j++) acc += fmaxf(base[(size_t)j * HIDF], 0.f);
    g_pooled[g * (3 * HIDF) + l * HIDF + t] = acc / fmaxf((float)n, 1.f);
}

// ---------------- MLP head + log_softmax -------------------------------------
__global__ void __launch_bounds__(128) k_head(const float* __restrict__ Wfc1,
                                              const float* __restrict__ bfc1,
                                              const float* __restrict__ Wfc2,
                                              const float* __restrict__ bfc2,
                                              float* __restrict__ out) {
    __shared__ float sP[3 * HIDF];
    __shared__ float sH[HIDF];
    __shared__ float sZ[2];
    int g = blockIdx.x;
    int t = threadIdx.x;
    for (int i = t; i < 3 * HIDF; i += 128) sP[i] = g_pooled[g * (3 * HIDF) + i];
    __syncthreads();
    float acc = bfc1[t];
#pragma unroll 8
    for (int k = 0; k < 3 * HIDF; k++) acc += sP[k] * Wfc1[k * HIDF + t];
    sH[t] = fmaxf(acc, 0.f);
    __syncthreads();
    if (t < 2) {
        float z = bfc2[t];
#pragma unroll 8
        for (int j = 0; j < HIDF; j++) z += sH[j] * Wfc2[j * 2 + t];
        sZ[t] = z;
    }
    __syncthreads();
    if (t == 0) {
        float z0 = sZ[0], z1 = sZ[1];
        float m = fmaxf(z0, z1);
        float lse = m + logf(expf(z0 - m) + expf(z1 - m));
        out[g * 2 + 0] = z0 - lse;
        out[g * 2 + 1] = z1 - lse;
    }
}

// ---------------- driver ------------------------------------------------------
extern "C" void kernel_launch(void* const* d_in, const int* in_sizes, int n_in,
                              void* d_out, int out_size) {
    const float* x        = (const float*)d_in[0];
    const void*  ei       = d_in[1];
    const void*  bat      = d_in[2];
    const float* W_conv   = (const float*)d_in[3];
    const float* b_conv   = (const float*)d_in[4];
    const float* bn_gamma = (const float*)d_in[5];
    const float* bn_beta  = (const float*)d_in[6];
    const float* bn_mean  = (const float*)d_in[7];
    const float* bn_var   = (const float*)d_in[8];
    const float* W_fc1    = (const float*)d_in[9];
    const float* b_fc1    = (const float*)d_in[10];
    const float* W_fc2    = (const float*)d_in[11];
    const float* b_fc2    = (const float*)d_in[12];
    float* out = (float*)d_out;

    k_detect<<<1, 32>>>((const int*)ei);
    k_init<<<(N_NODES + 255) / 256, 256>>>();
    k_edge<<<(E_EDGES + 255) / 256, 256>>>(ei);
    k_rsqrt<<<(N_NODES + 255) / 256, 256>>>();
    k_scan1<<<NB_SCAN, 256>>>();
    k_scan2<<<1, 512>>>();
    k_scan3<<<(N_NODES + 255) / 256, 256>>>();
    k_place<<<(E_EDGES + 255) / 256, 256>>>();
    k_fold_w<<<(3 * 8192 + 255) / 256, 256>>>(W_conv, bn_gamma, bn_var);
    k_fold_b<<<2, 256>>>(b_conv, bn_gamma, bn_beta, bn_mean, bn_var);

    for (int l = 0; l < 3; l++) {
        k_gemm<<<(N_NODES + 31) / 32, 256>>>(x, l - 1, l, (l > 0) ? 1 : 0);
        k_aggr<<<(N_NODES * 32 + 255) / 256, 256>>>(l);
    }

    k_batch<<<(N_NODES + 255) / 256, 256>>>(bat);
    dim3 pg(GG, 3);
    k_pool<<<pg, 128>>>();
    k_head<<<GG, 128>>>(W_fc1, b_fc1, W_fc2, b_fc2, out);
}

// round 6
// speedup vs baseline: 1.1575x; 1.1575x over previous
#include <cuda_runtime.h>
#include <cuda_fp16.h>

#define N_NODES 100000
#define E_EDGES 3200000
#define HIDF    128
#define GG      64
#define BN_EPS  1e-5f
#define NB_SCAN 391   // ceil(N_NODES/256)

// ---------------- static device scratch (no runtime allocations) -------------
__device__ int   g_is64;                          // 1 if index inputs are int64
__device__ float g_dis[N_NODES];                  // rsqrt(degree)
__device__ int   g_hist[N_NODES];                 // in-degree (excl self-loop)
__device__ int   g_off[N_NODES];                  // exclusive prefix of hist
__device__ int   g_cursor[N_NODES];               // placement cursors
__device__ int   g_bsum[512];                     // block sums for scan
__device__ int   g_row[E_EDGES];
__device__ int   g_col[E_EDGES];
__device__ __align__(16) float2 g_sedge[E_EDGES];  // dest-sorted {src(bits), norm}
__device__ __align__(16) __half g_xwh[(size_t)N_NODES * HIDF]; // fp16 transformed feats
__device__ __align__(16) float g_hbuf[3u * N_NODES * HIDF];    // per-layer pre-ReLU
__device__ __align__(16) float g_Wp[3 * 2 * 64 * 64];          // BN-folded weights
__device__ __align__(16) float g_bp[3 * HIDF];                 // BN-folded bias
__device__ float g_pooled[GG * 3 * HIDF];
__device__ int   g_cnt[GG];
__device__ int   g_start[GG];

// ---------------- dtype detection -------------------------------------------
__global__ void k_detect(const int* __restrict__ ei32) {
    if (threadIdx.x == 0 && blockIdx.x == 0) {
        int odd_zero = 1;
        for (int i = 0; i < 64; i++)
            if (ei32[2 * i + 1] != 0) odd_zero = 0;
        g_is64 = odd_zero;
    }
}

// ---------------- init -------------------------------------------------------
__global__ void k_init() {
    int i = blockIdx.x * blockDim.x + threadIdx.x;
    if (i < N_NODES) g_hist[i] = 0;
    if (i < GG) { g_cnt[i] = 0; g_start[i] = 0; }
}

// edge load: -> int32 row/col, histogram over destination
__global__ void k_edge(const void* __restrict__ eiv) {
    int e = blockIdx.x * blockDim.x + threadIdx.x;
    if (e >= E_EDGES) return;
    int r, c;
    if (g_is64) {
        const long long* ei = (const long long*)eiv;
        r = (int)ei[e];
        c = (int)ei[(size_t)E_EDGES + e];
    } else {
        const int* ei = (const int*)eiv;
        r = ei[e];
        c = ei[E_EDGES + e];
    }
    g_row[e] = r;
    g_col[e] = c;
    atomicAdd(&g_hist[c], 1);
}

// ---------------- scan level 1 (+ dis = rsqrt(deg+1)) ------------------------
__global__ void __launch_bounds__(256) k_scan1() {
    __shared__ int sh[256];
    int b = blockIdx.x, t = threadIdx.x;
    int i = b * 256 + t;
    int v = (i < N_NODES) ? g_hist[i] : 0;
    if (i < N_NODES) g_dis[i] = rsqrtf((float)(v + 1));
    sh[t] = v;
    __syncthreads();
    for (int o = 1; o < 256; o <<= 1) {
        int u = (t >= o) ? sh[t - o] : 0;
        __syncthreads();
        sh[t] += u;
        __syncthreads();
    }
    if (i < N_NODES) g_off[i] = sh[t] - v;       // exclusive within block
    if (t == 255) g_bsum[b] = sh[255];
}

__global__ void __launch_bounds__(512) k_scan2() {
    __shared__ int sh[512];
    int t = threadIdx.x;
    int v = (t < NB_SCAN) ? g_bsum[t] : 0;
    sh[t] = v;
    __syncthreads();
    for (int o = 1; o < 512; o <<= 1) {
        int u = (t >= o) ? sh[t - o] : 0;
        __syncthreads();
        sh[t] += u;
        __syncthreads();
    }
    if (t < NB_SCAN) g_bsum[t] = sh[t] - v;      // exclusive block offsets
}

__global__ void k_scan3() {
    int i = blockIdx.x * blockDim.x + threadIdx.x;
    if (i >= N_NODES) return;
    int o = g_off[i] + g_bsum[i >> 8];
    g_off[i] = o;
    g_cursor[i] = o;
}

// place {src, norm} into dest-sorted order (one 8B store per edge)
__global__ void k_place() {
    int e = blockIdx.x * blockDim.x + threadIdx.x;
    if (e >= E_EDGES) return;
    int r = g_row[e];
    int c = g_col[e];
    int pos = atomicAdd(&g_cursor[c], 1);
    float nv = g_dis[r] * g_dis[c];
    g_sedge[pos] = make_float2(__int_as_float(r), nv);
}

// ---------------- BN folding -------------------------------------------------
__global__ void k_fold_w(const float* __restrict__ W, const float* __restrict__ gamma,
                         const float* __restrict__ var) {
    int idx = blockIdx.x * blockDim.x + threadIdx.x;
    if (idx >= 3 * 8192) return;
    int l = idx / 8192;
    int rem = idx - l * 8192;
    int p = rem / 4096;
    int j = rem & 63;
    int c = p * 64 + j;
    float sg = gamma[l * HIDF + c] * rsqrtf(var[l * HIDF + c] + BN_EPS);
    g_Wp[idx] = W[idx] * sg;
}

__global__ void k_fold_b(const float* __restrict__ b, const float* __restrict__ gamma,
                         const float* __restrict__ beta, const float* __restrict__ mean,
                         const float* __restrict__ var) {
    int idx = blockIdx.x * blockDim.x + threadIdx.x;
    if (idx >= 3 * HIDF) return;
    float sg = gamma[idx] * rsqrtf(var[idx] + BN_EPS);
    g_bp[idx] = b[idx] * sg + (beta[idx] - mean[idx] * sg);
}

// ---------------- block-diagonal GEMM -> fp16 xw ------------------------------
// 32-row tile, 256 threads. Static shared = 32KB (W) + 16KB (in) = 48KB.
__global__ void __launch_bounds__(256) k_gemm(const float* __restrict__ x,
                                              int src_layer, int layer, int relu_in) {
    __shared__ float sW[8192];        // [2][64][64]
    __shared__ float sIn[32 * HIDF];  // 32 rows x 128
    const float* in = (src_layer < 0) ? x : (g_hbuf + (size_t)src_layer * N_NODES * HIDF);
    int t = threadIdx.x;
    const float4* Wl4 = (const float4*)(g_Wp + layer * 8192);
#pragma unroll
    for (int i = 0; i < 8; i++) {
        int idx = t + i * 256;
        ((float4*)sW)[idx] = Wl4[idx];
    }
    int R0 = blockIdx.x * 32;
#pragma unroll
    for (int i = 0; i < 4; i++) {
        int idx = t + i * 256;
        int r = idx >> 5;
        int c4 = idx & 31;
        float4 v = make_float4(0.f, 0.f, 0.f, 0.f);
        if (R0 + r < N_NODES) v = ((const float4*)in)[(size_t)(R0 + r) * 32 + c4];
        if (relu_in) {
            v.x = fmaxf(v.x, 0.f); v.y = fmaxf(v.y, 0.f);
            v.z = fmaxf(v.z, 0.f); v.w = fmaxf(v.w, 0.f);
        }
        ((float4*)sIn)[idx] = v;
    }
    __syncthreads();

    int cg = t & 31;
    int rg = t >> 5;
    int p = cg >> 4;
    int c0 = cg * 4;
    int jn = c0 & 63;
    int r0 = rg * 4;
    float acc[4][4];
#pragma unroll
    for (int i = 0; i < 4; i++) { acc[i][0] = acc[i][1] = acc[i][2] = acc[i][3] = 0.f; }
    const float* sWp = sW + p * 4096;
    const float* sInp = sIn + p * 64;
#pragma unroll 4
    for (int k = 0; k < 64; k++) {
        float4 w = *(const float4*)(sWp + k * 64 + jn);
#pragma unroll
        for (int i = 0; i < 4; i++) {
            float a = sInp[(r0 + i) * HIDF + k];
            acc[i][0] += a * w.x; acc[i][1] += a * w.y;
            acc[i][2] += a * w.z; acc[i][3] += a * w.w;
        }
    }
#pragma unroll
    for (int i = 0; i < 4; i++) {
        int r = R0 + r0 + i;
        if (r < N_NODES) {
            __half2 p0 = __floats2half2_rn(acc[i][0], acc[i][1]);
            __half2 p1 = __floats2half2_rn(acc[i][2], acc[i][3]);
            uint2 st;
            *reinterpret_cast<__half2*>(&st.x) = p0;
            *reinterpret_cast<__half2*>(&st.y) = p1;
            *reinterpret_cast<uint2*>(g_xwh + (size_t)r * HIDF + c0) = st;
        }
    }
}

// ---------------- segmented gather-reduce: one warp per destination ----------
__global__ void __launch_bounds__(256) k_aggr(int layer) {
    int node = (blockIdx.x * 256 + threadIdx.x) >> 5;
    if (node >= N_NODES) return;
    int lane = threadIdx.x & 31;
    int s0 = g_off[node];
    int s1 = (node + 1 < N_NODES) ? g_off[node + 1] : E_EDGES;
    float dc = g_dis[node];

    // seed: bias + self-loop (norm = dc*dc), self feats from fp16 table
    float4 b = ((const float4*)g_bp)[layer * 32 + lane];
    uint2 sh = *reinterpret_cast<const uint2*>(g_xwh + (size_t)node * HIDF + lane * 4);
    float2 sa = __half22float2(*reinterpret_cast<__half2*>(&sh.x));
    float2 sb = __half22float2(*reinterpret_cast<__half2*>(&sh.y));
    float dd = dc * dc;
    float4 acc;
    acc.x = b.x + sa.x * dd; acc.y = b.y + sa.y * dd;
    acc.z = b.z + sb.x * dd; acc.w = b.w + sb.y * dd;

    for (int s = s0; s < s1; s += 32) {
        int idx = 0;
        float nv0 = 0.f;
        if (s + lane < s1) {
            float2 se = g_sedge[s + lane];
            idx = __float_as_int(se.x);
            nv0 = se.y;
        }
        int cnt = min(32, s1 - s);
        for (int j = 0; j < cnt; j++) {
            int r = __shfl_sync(0xffffffffu, idx, j);
            float nv = __shfl_sync(0xffffffffu, nv0, j);
            uint2 hv = __ldg(reinterpret_cast<const uint2*>(g_xwh + (size_t)r * HIDF) + lane);
            float2 fa = __half22float2(*reinterpret_cast<__half2*>(&hv.x));
            float2 fb = __half22float2(*reinterpret_cast<__half2*>(&hv.y));
            acc.x += fa.x * nv; acc.y += fa.y * nv;
            acc.z += fb.x * nv; acc.w += fb.y * nv;
        }
    }
    ((float4*)(g_hbuf + (size_t)layer * N_NODES * HIDF))[(size_t)node * 32 + lane] = acc;
}

// ---------------- batch counts + segment starts (batch is sorted) ------------
__global__ void k_batch(const void* __restrict__ bv) {
    int i = blockIdx.x * blockDim.x + threadIdx.x;
    if (i >= N_NODES) return;
    int b, bp = -1;
    if (g_is64) {
        const long long* bb = (const long long*)bv;
        b = (int)bb[i];
        if (i > 0) bp = (int)bb[i - 1];
    } else {
        const int* bb = (const int*)bv;
        b = bb[i];
        if (i > 0) bp = bb[i - 1];
    }
    atomicAdd(&g_cnt[b], 1);
    if (i == 0 || bp != b) g_start[b] = i;
}

// ---------------- mean pool with lazy ReLU -----------------------------------
__global__ void __launch_bounds__(128) k_pool() {
    int g = blockIdx.x;
    int l = blockIdx.y;
    int t = threadIdx.x;
    int s = g_start[g];
    int n = g_cnt[g];
    const float* base = g_hbuf + ((size_t)l * N_NODES + s) * HIDF + t;
    float acc = 0.f;
    for (int j = 0; j < n; j++) acc += fmaxf(base[(size_t)j * HIDF], 0.f);
    g_pooled[g * (3 * HIDF) + l * HIDF + t] = acc / fmaxf((float)n, 1.f);
}

// ---------------- MLP head + log_softmax -------------------------------------
__global__ void __launch_bounds__(128) k_head(const float* __restrict__ Wfc1,
                                              const float* __restrict__ bfc1,
                                              const float* __restrict__ Wfc2,
                                              const float* __restrict__ bfc2,
                                              float* __restrict__ out) {
    __shared__ float sP[3 * HIDF];
    __shared__ float sH[HIDF];
    __shared__ float sZ[2];
    int g = blockIdx.x;
    int t = threadIdx.x;
    for (int i = t; i < 3 * HIDF; i += 128) sP[i] = g_pooled[g * (3 * HIDF) + i];
    __syncthreads();
    float acc = bfc1[t];
#pragma unroll 8
    for (int k = 0; k < 3 * HIDF; k++) acc += sP[k] * Wfc1[k * HIDF + t];
    sH[t] = fmaxf(acc, 0.f);
    __syncthreads();
    if (t < 2) {
        float z = bfc2[t];
#pragma unroll 8
        for (int j = 0; j < HIDF; j++) z += sH[j] * Wfc2[j * 2 + t];
        sZ[t] = z;
    }
    __syncthreads();
    if (t == 0) {
        float z0 = sZ[0], z1 = sZ[1];
        float m = fmaxf(z0, z1);
        float lse = m + logf(expf(z0 - m) + expf(z1 - m));
        out[g * 2 + 0] = z0 - lse;
        out[g * 2 + 1] = z1 - lse;
    }
}

// ---------------- driver ------------------------------------------------------
extern "C" void kernel_launch(void* const* d_in, const int* in_sizes, int n_in,
                              void* d_out, int out_size) {
    const float* x        = (const float*)d_in[0];
    const void*  ei       = d_in[1];
    const void*  bat      = d_in[2];
    const float* W_conv   = (const float*)d_in[3];
    const float* b_conv   = (const float*)d_in[4];
    const float* bn_gamma = (const float*)d_in[5];
    const float* bn_beta  = (const float*)d_in[6];
    const float* bn_mean  = (const float*)d_in[7];
    const float* bn_var   = (const float*)d_in[8];
    const float* W_fc1    = (const float*)d_in[9];
    const float* b_fc1    = (const float*)d_in[10];
    const float* W_fc2    = (const float*)d_in[11];
    const float* b_fc2    = (const float*)d_in[12];
    float* out = (float*)d_out;

    k_detect<<<1, 32>>>((const int*)ei);
    k_init<<<(N_NODES + 255) / 256, 256>>>();
    k_edge<<<(E_EDGES + 255) / 256, 256>>>(ei);
    k_scan1<<<NB_SCAN, 256>>>();
    k_scan2<<<1, 512>>>();
    k_scan3<<<(N_NODES + 255) / 256, 256>>>();
    k_place<<<(E_EDGES + 255) / 256, 256>>>();
    k_fold_w<<<(3 * 8192 + 255) / 256, 256>>>(W_conv, bn_gamma, bn_var);
    k_fold_b<<<2, 256>>>(b_conv, bn_gamma, bn_beta, bn_mean, bn_var);

    for (int l = 0; l < 3; l++) {
        k_gemm<<<(N_NODES + 31) / 32, 256>>>(x, l - 1, l, (l > 0) ? 1 : 0);
        k_aggr<<<(N_NODES * 32 + 255) / 256, 256>>>(l);
    }

    k_batch<<<(N_NODES + 255) / 256, 256>>>(bat);
    dim3 pg(GG, 3);
    k_pool<<<pg, 128>>>();
    k_head<<<GG, 128>>>(W_fc1, b_fc1, W_fc2, b_fc2, out);
}